// round 2
// baseline (speedup 1.0000x reference)
#include <cuda_runtime.h>
#include <math.h>

// Problem constants
#define BB 8
#define CC 512
#define LL 2048

// Scratch (static device globals — no allocation)
__device__ float g_q[BB * CC * LL];
__device__ float g_k[BB * CC * LL];
__device__ float g_v[BB * CC * LL];
__device__ float g_s[(size_t)BB * LL * LL];

// ---------------------------------------------------------------------------
// Tiled fp32 GEMM body: C[m,n] = scale * sum_k A(m,k)*B(k,n) + bias[m]
//   TA=false: A row-major MxK (A[m*lda+k]);  TA=true: A is KxM (A[k*lda+m])
//   TB=false: B row-major KxN (B[k*ldb+n]);  TB=true: B is NxK (B[n*ldb+k])
// Block computes 64x64 of C; 256 threads, 4x4 per thread, BK=16.
// All dims are multiples of 64 (K multiple of 16) for this problem -> no guards.
// ---------------------------------------------------------------------------
constexpr int BM = 64, BN = 64, BK = 16, PAD = 68;

template <bool TA, bool TB>
__device__ __forceinline__ void gemm_body(
    const float* __restrict__ A, const float* __restrict__ B,
    float* __restrict__ C, int K,
    int lda, int ldb, int ldc,
    float scale, const float* __restrict__ bias)
{
    __shared__ float As[BK][PAD];
    __shared__ float Bs[BK][PAD];

    const int tid = threadIdx.x;        // 0..255
    const int tx = tid & 15;            // 0..15
    const int ty = tid >> 4;            // 0..15
    const int m0 = blockIdx.y * BM;
    const int n0 = blockIdx.x * BN;

    float acc[4][4];
#pragma unroll
    for (int i = 0; i < 4; i++)
#pragma unroll
        for (int j = 0; j < 4; j++) acc[i][j] = 0.0f;

    for (int k0 = 0; k0 < K; k0 += BK) {
        // ---- load A tile -> As[k][m] ----
        if (TA) {
            const int m = tid & 63;
            const int kk = tid >> 6;    // 0..3
#pragma unroll
            for (int p = 0; p < BK; p += 4)
                As[kk + p][m] = A[(size_t)(k0 + kk + p) * lda + (m0 + m)];
        } else {
            const int kk = tid & 15;
            const int m = tid >> 4;     // 0..15
#pragma unroll
            for (int p = 0; p < BM; p += 16)
                As[kk][m + p] = A[(size_t)(m0 + m + p) * lda + (k0 + kk)];
        }
        // ---- load B tile -> Bs[k][n] ----
        if (TB) {
            const int kk = tid & 15;
            const int n = tid >> 4;
#pragma unroll
            for (int p = 0; p < BN; p += 16)
                Bs[kk][n + p] = B[(size_t)(n0 + n + p) * ldb + (k0 + kk)];
        } else {
            const int n = tid & 63;
            const int kk = tid >> 6;
#pragma unroll
            for (int p = 0; p < BK; p += 4)
                Bs[kk + p][n] = B[(size_t)(k0 + kk + p) * ldb + (n0 + n)];
        }
        __syncthreads();

#pragma unroll
        for (int kk = 0; kk < BK; kk++) {
            const float4 a4 = *(const float4*)&As[kk][ty * 4];
            const float4 b4 = *(const float4*)&Bs[kk][tx * 4];
            const float av[4] = {a4.x, a4.y, a4.z, a4.w};
            const float bv[4] = {b4.x, b4.y, b4.z, b4.w};
#pragma unroll
            for (int i = 0; i < 4; i++)
#pragma unroll
                for (int j = 0; j < 4; j++)
                    acc[i][j] = fmaf(av[i], bv[j], acc[i][j]);
        }
        __syncthreads();
    }

    // epilogue
#pragma unroll
    for (int i = 0; i < 4; i++) {
        const int m = m0 + ty * 4 + i;
        const float bvv = bias ? bias[m] : 0.0f;
#pragma unroll
        for (int j = 0; j < 4; j++) {
            const int n = n0 + tx * 4 + j;
            C[(size_t)m * ldc + n] = acc[i][j] * scale + bvv;
        }
    }
}

// ---------------------------------------------------------------------------
// Kernel 1: QKV projection.  q[b,o,l] = sum_i W[o,i]*x[b,i,l] + bias[o]
// grid = (LL/64, CC/64, 3*BB) ; z encodes (proj, batch)
// ---------------------------------------------------------------------------
__global__ __launch_bounds__(256) void qkv_kernel(
    const float* __restrict__ x,
    const float* __restrict__ Wq, const float* __restrict__ bq,
    const float* __restrict__ Wk, const float* __restrict__ bk,
    const float* __restrict__ Wv, const float* __restrict__ bv)
{
    const int z = blockIdx.z;
    const int p = z >> 3;       // 0=q, 1=k, 2=v
    const int b = z & 7;
    const float* W  = (p == 0) ? Wq : (p == 1) ? Wk : Wv;
    const float* bi = (p == 0) ? bq : (p == 1) ? bk : bv;
    float* out = ((p == 0) ? g_q : (p == 1) ? g_k : g_v) + (size_t)b * CC * LL;
    const float* xb = x + (size_t)b * CC * LL;
    // A = W (CCxCC row-major), B = xb (CCxLL row-major)
    gemm_body<false, false>(W, xb, out, CC, CC, LL, LL, 1.0f, bi);
}

// ---------------------------------------------------------------------------
// Kernel 2: scores[b,l,m] = (1/sqrt(C)) * sum_c q[b,c,l]*k[b,c,m]
// TN GEMM: A = Q (KxM layout), B = K (KxN layout). grid = (32, 32, BB)
// ---------------------------------------------------------------------------
__global__ __launch_bounds__(256) void scores_kernel()
{
    const int b = blockIdx.z;
    const float* Q  = g_q + (size_t)b * CC * LL;
    const float* Kp = g_k + (size_t)b * CC * LL;
    float* S = g_s + (size_t)b * LL * LL;
    const float scale = 0.044194173824159216f;  // 1/sqrt(512)
    gemm_body<true, false>(Q, Kp, S, CC, LL, LL, LL, scale, nullptr);
}

// ---------------------------------------------------------------------------
// Kernel 3: row softmax over m.  One block (256 thr) per row of 2048.
// grid = BB*LL blocks.
// ---------------------------------------------------------------------------
__global__ __launch_bounds__(256) void softmax_kernel()
{
    const int tid = threadIdx.x;
    float* row = g_s + (size_t)blockIdx.x * LL;

    float v[8];
    float mx = -3.402823466e38f;
#pragma unroll
    for (int i = 0; i < 8; i++) {
        v[i] = row[tid + (i << 8)];
        mx = fmaxf(mx, v[i]);
    }
    __shared__ float red[256];
    red[tid] = mx;
    __syncthreads();
    for (int s = 128; s >= 1; s >>= 1) {
        if (tid < s) red[tid] = fmaxf(red[tid], red[tid + s]);
        __syncthreads();
    }
    mx = red[0];
    __syncthreads();

    float sum = 0.0f;
#pragma unroll
    for (int i = 0; i < 8; i++) {
        v[i] = __expf(v[i] - mx);
        sum += v[i];
    }
    red[tid] = sum;
    __syncthreads();
    for (int s = 128; s >= 1; s >>= 1) {
        if (tid < s) red[tid] += red[tid + s];
        __syncthreads();
    }
    const float inv = __frcp_rn(red[0]);
#pragma unroll
    for (int i = 0; i < 8; i++)
        row[tid + (i << 8)] = v[i] * inv;
}

// ---------------------------------------------------------------------------
// Kernel 4: out[b,c,l] = sum_m v[b,c,m] * attn[b,l,m]   (NT GEMM)
// A = V (CCxLL row-major), B = P (LLxLL, transposed access). grid = (32, 8, BB)
// ---------------------------------------------------------------------------
__global__ __launch_bounds__(256) void out_kernel(float* __restrict__ out)
{
    const int b = blockIdx.z;
    const float* V = g_v + (size_t)b * CC * LL;
    const float* P = g_s + (size_t)b * LL * LL;
    float* O = out + (size_t)b * CC * LL;
    gemm_body<false, true>(V, P, O, LL, LL, LL, LL, 1.0f, nullptr);
}

// ---------------------------------------------------------------------------
extern "C" void kernel_launch(void* const* d_in, const int* in_sizes, int n_in,
                              void* d_out, int out_size)
{
    const float* x  = (const float*)d_in[0];
    const float* Wq = (const float*)d_in[1];
    const float* bq = (const float*)d_in[2];
    const float* Wk = (const float*)d_in[3];
    const float* bk = (const float*)d_in[4];
    const float* Wv = (const float*)d_in[5];
    const float* bv = (const float*)d_in[6];
    float* out = (float*)d_out;

    dim3 blk(256);

    // 1) QKV projections: 24 GEMMs of [512x512]x[512x2048]
    dim3 g1(LL / BN, CC / BM, 3 * BB);
    qkv_kernel<<<g1, blk>>>(x, Wq, bq, Wk, bk, Wv, bv);

    // 2) scores = Q^T K / sqrt(C): per-batch [2048x2048], K=512
    dim3 g2(LL / BN, LL / BM, BB);
    scores_kernel<<<g2, blk>>>();

    // 3) softmax over last dim
    softmax_kernel<<<BB * LL, blk>>>();

    // 4) out = V @ attn^T: per-batch [512x2048], K=2048
    dim3 g4(LL / BN, CC / BM, BB);
    out_kernel<<<g4, blk>>>(out);
}

// round 6
// speedup vs baseline: 2.3165x; 2.3165x over previous
#include <cuda_runtime.h>
#include <math.h>

#define BB 8
#define CC 512
#define LL 2048

// Scratch (static device globals — no allocation)
__device__ float g_q[BB * CC * LL];
__device__ float g_k[BB * CC * LL];
__device__ float g_v[BB * CC * LL];
__device__ float g_s[(size_t)BB * LL * LL];

// ---------------------------------------------------------------------------
// tf32 mma.sync GEMM: C[m,n] = scale * sum_k A(m,k)*B(k,n) + bias[m]
//   TA=false: A row-major MxK (A[m*lda+k]);  TA=true: A is KxM (A[k*lda+m])
//   TB=false: B row-major KxN (B[k*ldb+n]);  TB=true: B is NxK (B[n*ldb+k])
// Block: 128x128, 256 threads (8 warps, 2 in M x 4 in N), warp tile 64x32.
// BK=16 -> 2 k-steps of m16n8k8 per tile. All dims multiples of 128/16.
// ---------------------------------------------------------------------------
constexpr int BM = 128, BN = 128, BK = 16;
constexpr int SA = 136;   // padded row stride (136 mod 32 == 8 -> conflict-free frags)

__device__ __forceinline__ unsigned f2tf(float f) {
    unsigned u;
    asm("cvt.rna.tf32.f32 %0, %1;" : "=r"(u) : "f"(f));
    return u;
}

__device__ __forceinline__ void mma_tf32(float* d, const unsigned* a, const unsigned* b) {
    asm volatile(
        "mma.sync.aligned.m16n8k8.row.col.f32.tf32.tf32.f32 "
        "{%0,%1,%2,%3}, {%4,%5,%6,%7}, {%8,%9}, {%0,%1,%2,%3};"
        : "+f"(d[0]), "+f"(d[1]), "+f"(d[2]), "+f"(d[3])
        : "r"(a[0]), "r"(a[1]), "r"(a[2]), "r"(a[3]), "r"(b[0]), "r"(b[1]));
}

template <bool TA, bool TB>
__device__ __forceinline__ void gemm_body(
    const float* __restrict__ A, const float* __restrict__ B,
    float* __restrict__ C, int K,
    int lda, int ldb, int ldc,
    float scale, const float* __restrict__ bias)
{
    __shared__ unsigned As[BK][SA];
    __shared__ unsigned Bs[BK][SA];

    const int tid  = threadIdx.x;
    const int lane = tid & 31;
    const int warp = tid >> 5;
    const int wm = warp & 1;        // 0..1  (M dir, 64 rows each)
    const int wn = warp >> 1;       // 0..3  (N dir, 32 cols each)
    const int r = lane >> 2;        // groupID           0..7
    const int c = lane & 3;         // threadID_in_group 0..3
    const int m0 = blockIdx.y * BM;
    const int n0 = blockIdx.x * BN;

    float acc[4][4][4];
#pragma unroll
    for (int i = 0; i < 4; i++)
#pragma unroll
        for (int j = 0; j < 4; j++)
#pragma unroll
            for (int q = 0; q < 4; q++) acc[i][j][q] = 0.0f;

    float4 pa[2], pb[2];

    // ---- global loads into regs (2 float4 each for A and B tile) ----
    auto ldA = [&](int k0) {
#pragma unroll
        for (int it = 0; it < 2; it++) {
            const int chunk = tid + 256 * it;
            if (!TA) {
                const int m = chunk & 127, k4 = chunk >> 7;          // k4: 0..3
                pa[it] = *(const float4*)&A[(size_t)(m0 + m) * lda + k0 + 4 * k4];
            } else {
                const int kk = chunk >> 5, m4 = chunk & 31;          // kk: 0..15
                pa[it] = *(const float4*)&A[(size_t)(k0 + kk) * lda + m0 + 4 * m4];
            }
        }
    };
    auto ldB = [&](int k0) {
#pragma unroll
        for (int it = 0; it < 2; it++) {
            const int chunk = tid + 256 * it;
            if (!TB) {
                const int kk = chunk >> 5, n4 = chunk & 31;
                pb[it] = *(const float4*)&B[(size_t)(k0 + kk) * ldb + n0 + 4 * n4];
            } else {
                const int n = chunk & 127, k4 = chunk >> 7;
                pb[it] = *(const float4*)&B[(size_t)(n0 + n) * ldb + k0 + 4 * k4];
            }
        }
    };
    auto stA = [&]() {
#pragma unroll
        for (int it = 0; it < 2; it++) {
            const int chunk = tid + 256 * it;
            if (!TA) {
                const int m = chunk & 127, k4 = chunk >> 7;
                As[4 * k4 + 0][m] = f2tf(pa[it].x);
                As[4 * k4 + 1][m] = f2tf(pa[it].y);
                As[4 * k4 + 2][m] = f2tf(pa[it].z);
                As[4 * k4 + 3][m] = f2tf(pa[it].w);
            } else {
                const int kk = chunk >> 5, m4 = chunk & 31;
                uint4 v = make_uint4(f2tf(pa[it].x), f2tf(pa[it].y),
                                     f2tf(pa[it].z), f2tf(pa[it].w));
                *(uint4*)&As[kk][4 * m4] = v;
            }
        }
    };
    auto stB = [&]() {
#pragma unroll
        for (int it = 0; it < 2; it++) {
            const int chunk = tid + 256 * it;
            if (!TB) {
                const int kk = chunk >> 5, n4 = chunk & 31;
                uint4 v = make_uint4(f2tf(pb[it].x), f2tf(pb[it].y),
                                     f2tf(pb[it].z), f2tf(pb[it].w));
                *(uint4*)&Bs[kk][4 * n4] = v;
            } else {
                const int n = chunk & 127, k4 = chunk >> 7;
                Bs[4 * k4 + 0][n] = f2tf(pb[it].x);
                Bs[4 * k4 + 1][n] = f2tf(pb[it].y);
                Bs[4 * k4 + 2][n] = f2tf(pb[it].z);
                Bs[4 * k4 + 3][n] = f2tf(pb[it].w);
            }
        }
    };
    auto compute = [&]() {
#pragma unroll
        for (int ks = 0; ks < 2; ks++) {
            const int kb = ks * 8;
            unsigned af[4][4], bf[4][2];
#pragma unroll
            for (int i = 0; i < 4; i++) {
                const int mb = wm * 64 + i * 16;
                af[i][0] = As[kb + c][mb + r];
                af[i][1] = As[kb + c][mb + r + 8];
                af[i][2] = As[kb + c + 4][mb + r];
                af[i][3] = As[kb + c + 4][mb + r + 8];
            }
#pragma unroll
            for (int j = 0; j < 4; j++) {
                const int nb = wn * 32 + j * 8;
                bf[j][0] = Bs[kb + c][nb + r];
                bf[j][1] = Bs[kb + c + 4][nb + r];
            }
#pragma unroll
            for (int i = 0; i < 4; i++)
#pragma unroll
                for (int j = 0; j < 4; j++)
                    mma_tf32(acc[i][j], af[i], bf[j]);
        }
    };

    // ---- pipelined mainloop ----
    ldA(0); ldB(0);
    stA(); stB();
    __syncthreads();
    for (int k0 = BK;; k0 += BK) {
        const bool more = (k0 < K);
        if (more) { ldA(k0); ldB(k0); }
        compute();
        if (!more) break;
        __syncthreads();
        stA(); stB();
        __syncthreads();
    }

    // ---- epilogue ----
#pragma unroll
    for (int i = 0; i < 4; i++) {
        const int m = m0 + wm * 64 + i * 16 + r;
        const float bv0 = bias ? __ldg(&bias[m])     : 0.0f;
        const float bv1 = bias ? __ldg(&bias[m + 8]) : 0.0f;
#pragma unroll
        for (int j = 0; j < 4; j++) {
            const int n = n0 + wn * 32 + j * 8 + 2 * c;
            float2 v0 = make_float2(acc[i][j][0] * scale + bv0,
                                    acc[i][j][1] * scale + bv0);
            *(float2*)&C[(size_t)m * ldc + n] = v0;
            float2 v1 = make_float2(acc[i][j][2] * scale + bv1,
                                    acc[i][j][3] * scale + bv1);
            *(float2*)&C[(size_t)(m + 8) * ldc + n] = v1;
        }
    }
}

// ---------------------------------------------------------------------------
// Kernel 1: QKV projection. grid = (LL/128, CC/128, 3*BB)
// ---------------------------------------------------------------------------
__global__ __launch_bounds__(256) void qkv_kernel(
    const float* __restrict__ x,
    const float* __restrict__ Wq, const float* __restrict__ bq,
    const float* __restrict__ Wk, const float* __restrict__ bk,
    const float* __restrict__ Wv, const float* __restrict__ bv)
{
    const int z = blockIdx.z;
    const int p = z >> 3;
    const int b = z & 7;
    const float* W  = (p == 0) ? Wq : (p == 1) ? Wk : Wv;
    const float* bi = (p == 0) ? bq : (p == 1) ? bk : bv;
    float* out = ((p == 0) ? g_q : (p == 1) ? g_k : g_v) + (size_t)b * CC * LL;
    const float* xb = x + (size_t)b * CC * LL;
    gemm_body<false, false>(W, xb, out, CC, CC, LL, LL, 1.0f, bi);
}

// ---------------------------------------------------------------------------
// Kernel 2: scores = Q^T K / sqrt(C). grid = (LL/128, LL/128, BB)
// ---------------------------------------------------------------------------
__global__ __launch_bounds__(256) void scores_kernel()
{
    const int b = blockIdx.z;
    const float* Q  = g_q + (size_t)b * CC * LL;
    const float* Kp = g_k + (size_t)b * CC * LL;
    float* S = g_s + (size_t)b * LL * LL;
    gemm_body<true, false>(Q, Kp, S, CC, LL, LL, LL,
                           0.044194173824159216f, nullptr);
}

// ---------------------------------------------------------------------------
// Kernel 3: row softmax over m. One block per row. grid = BB*LL
// ---------------------------------------------------------------------------
__global__ __launch_bounds__(256) void softmax_kernel()
{
    const int tid = threadIdx.x;
    float* row = g_s + (size_t)blockIdx.x * LL;

    float v[8];
    float mx = -3.402823466e38f;
#pragma unroll
    for (int i = 0; i < 8; i++) {
        v[i] = row[tid + (i << 8)];
        mx = fmaxf(mx, v[i]);
    }
    __shared__ float red[256];
    red[tid] = mx;
    __syncthreads();
    for (int s = 128; s >= 1; s >>= 1) {
        if (tid < s) red[tid] = fmaxf(red[tid], red[tid + s]);
        __syncthreads();
    }
    mx = red[0];
    __syncthreads();

    float sum = 0.0f;
#pragma unroll
    for (int i = 0; i < 8; i++) {
        v[i] = __expf(v[i] - mx);
        sum += v[i];
    }
    red[tid] = sum;
    __syncthreads();
    for (int s = 128; s >= 1; s >>= 1) {
        if (tid < s) red[tid] += red[tid + s];
        __syncthreads();
    }
    const float inv = __frcp_rn(red[0]);
#pragma unroll
    for (int i = 0; i < 8; i++)
        row[tid + (i << 8)] = v[i] * inv;
}

// ---------------------------------------------------------------------------
// Kernel 4: out = V @ attn^T. grid = (LL/128, CC/128, BB)
// ---------------------------------------------------------------------------
__global__ __launch_bounds__(256) void out_kernel(float* __restrict__ out)
{
    const int b = blockIdx.z;
    const float* V = g_v + (size_t)b * CC * LL;
    const float* P = g_s + (size_t)b * LL * LL;
    float* O = out + (size_t)b * CC * LL;
    gemm_body<false, true>(V, P, O, LL, LL, LL, LL, 1.0f, nullptr);
}

// ---------------------------------------------------------------------------
extern "C" void kernel_launch(void* const* d_in, const int* in_sizes, int n_in,
                              void* d_out, int out_size)
{
    const float* x  = (const float*)d_in[0];
    const float* Wq = (const float*)d_in[1];
    const float* bq = (const float*)d_in[2];
    const float* Wk = (const float*)d_in[3];
    const float* bk = (const float*)d_in[4];
    const float* Wv = (const float*)d_in[5];
    const float* bv = (const float*)d_in[6];
    float* out = (float*)d_out;

    dim3 blk(256);

    dim3 g1(LL / BN, CC / BM, 3 * BB);
    qkv_kernel<<<g1, blk>>>(x, Wq, bq, Wk, bk, Wv, bv);

    dim3 g2(LL / BN, LL / BM, BB);
    scores_kernel<<<g2, blk>>>();

    softmax_kernel<<<BB * LL, blk>>>();

    dim3 g4(LL / BN, CC / BM, BB);
    out_kernel<<<g4, blk>>>(out);
}